// round 1
// baseline (speedup 1.0000x reference)
#include <cuda_runtime.h>
#include <cuda_fp16.h>
#include <cstdint>

// Problem constants (fixed by setup_inputs)
#define M_DIM 2048
#define K_DIM 4096
#define N_DIM 11008
#define NPACK (N_DIM / 8)   // 1376 packed int32 columns

// Tiling
#define BM 128
#define BN 128
#define BK 32
#define KT (K_DIM / BK)     // 128 k-tiles
#define LDA 40              // A smem row stride in halves (80B -> conflict-free ldmatrix)

__device__ __forceinline__ unsigned smem_addr(const void* p) {
    return (unsigned)__cvta_generic_to_shared(p);
}

__device__ __forceinline__ void ldsm_x4(unsigned& r0, unsigned& r1, unsigned& r2, unsigned& r3,
                                        unsigned addr) {
    asm volatile("ldmatrix.sync.aligned.m8n8.x4.shared.b16 {%0,%1,%2,%3}, [%4];"
                 : "=r"(r0), "=r"(r1), "=r"(r2), "=r"(r3)
                 : "r"(addr));
}

__device__ __forceinline__ void ldsm_x4_t(unsigned& r0, unsigned& r1, unsigned& r2, unsigned& r3,
                                          unsigned addr) {
    asm volatile("ldmatrix.sync.aligned.m8n8.x4.trans.shared.b16 {%0,%1,%2,%3}, [%4];"
                 : "=r"(r0), "=r"(r1), "=r"(r2), "=r"(r3)
                 : "r"(addr));
}

__device__ __forceinline__ void mma16816(float* c, const unsigned* a, unsigned b0, unsigned b1) {
    asm volatile(
        "mma.sync.aligned.m16n8k16.row.col.f32.f16.f16.f32 "
        "{%0,%1,%2,%3}, {%4,%5,%6,%7}, {%8,%9}, {%0,%1,%2,%3};"
        : "+f"(c[0]), "+f"(c[1]), "+f"(c[2]), "+f"(c[3])
        : "r"(a[0]), "r"(a[1]), "r"(a[2]), "r"(a[3]), "r"(b0), "r"(b1));
}

__global__ void __launch_bounds__(256, 1)
awq_gemm_kernel(const float* __restrict__ x, const int* __restrict__ qw,
                const int* __restrict__ qz, const float* __restrict__ sc,
                float* __restrict__ out)
{
    __shared__ __half As[2][BM * LDA];   // 2 * 128*40*2 = 20480 B
    __shared__ __half Bs[2][BK * BN];    // 2 * 32*128*2 = 16384 B

    const int tid = threadIdx.x;
    const int bx = blockIdx.x;           // N tile index, 0..85
    const int by = blockIdx.y;           // M tile index, 0..15
    const int m0 = by * BM;
    const int n0 = bx * BN;
    const int c0 = bx * (BN / 8);        // packed-column base

    const int warp = tid >> 5, lane = tid & 31;
    const int wm = (warp & 3) * 32;      // warp M offset inside CTA tile
    const int wn = (warp >> 2) * 64;     // warp N offset inside CTA tile

    // gmem staging maps
    const int arow = tid >> 3;           // 0..31, A row (step 32)
    const int af4  = tid & 7;            // A float4 column 0..7
    const int brow = tid >> 3;           // 0..31, B k-row
    const int bc   = (tid & 7) * 2;      // packed column pair base 0..14 (local)

    float4 aReg[4];
    int2   bReg;
    int2   zReg;
    float4 sReg[4];                      // 16 scales covering n-local [bc*8, bc*8+16)

    float acc[2][8][4];
#pragma unroll
    for (int i = 0; i < 2; i++)
#pragma unroll
        for (int j = 0; j < 8; j++)
#pragma unroll
            for (int q = 0; q < 4; q++) acc[i][j][q] = 0.f;

    auto load_raw = [&](int it) {
        const int k0 = it * BK;
#pragma unroll
        for (int i = 0; i < 4; i++) {
            int r = arow + i * 32;
            aReg[i] = *reinterpret_cast<const float4*>(
                x + (size_t)(m0 + r) * K_DIM + k0 + af4 * 4);
        }
        bReg = *reinterpret_cast<const int2*>(qw + (size_t)(k0 + brow) * NPACK + c0 + bc);
        if ((it & 3) == 0) {             // new quantization group (G=128 = 4 k-tiles)
            const int g = k0 >> 7;
            zReg = *reinterpret_cast<const int2*>(qz + (size_t)g * NPACK + c0 + bc);
            const float* sp = sc + (size_t)g * N_DIM + n0 + bc * 8;
            sReg[0] = *reinterpret_cast<const float4*>(sp + 0);
            sReg[1] = *reinterpret_cast<const float4*>(sp + 4);
            sReg[2] = *reinterpret_cast<const float4*>(sp + 8);
            sReg[3] = *reinterpret_cast<const float4*>(sp + 12);
        }
    };

    auto store_smem = [&](int buf) {
        // A: fp32 -> fp16 convert into stride-40 rows
#pragma unroll
        for (int i = 0; i < 4; i++) {
            int r = arow + i * 32;
            __half2 h01 = __floats2half2_rn(aReg[i].x, aReg[i].y);
            __half2 h23 = __floats2half2_rn(aReg[i].z, aReg[i].w);
            uint2 u = make_uint2(*reinterpret_cast<unsigned*>(&h01),
                                 *reinterpret_cast<unsigned*>(&h23));
            *reinterpret_cast<uint2*>(&As[buf][r * LDA + af4 * 4]) = u;
        }
        // B: AWQ dequant, one 16B chunk per packed int32, XOR swizzle by (k&7)
        const float* sA = reinterpret_cast<const float*>(sReg);
#pragma unroll
        for (int p = 0; p < 2; p++) {
            int packed = p ? bReg.y : bReg.x;
            int zpk    = p ? zReg.y : zReg.x;
            unsigned h[4];
#pragma unroll
            for (int mp = 0; mp < 4; mp++) {
                const int m0i = mp * 2;
                const int m1i = mp * 2 + 1;
                // AWQ nibble order: logical pos m lives at shift ((m&1)*4 + (m>>1)) * 4
                const int sh0 = (m0i & 1) * 16 + (m0i >> 1) * 4;
                const int sh1 = (m1i & 1) * 16 + (m1i >> 1) * 4;
                int q0 = (packed >> sh0) & 0xF;
                int z0 = (zpk    >> sh0) & 0xF;
                int q1 = (packed >> sh1) & 0xF;
                int z1 = (zpk    >> sh1) & 0xF;
                float w0 = (float)(q0 - z0) * sA[p * 8 + m0i];
                float w1 = (float)(q1 - z1) * sA[p * 8 + m1i];
                __half2 hh = __floats2half2_rn(w0, w1);
                h[mp] = *reinterpret_cast<unsigned*>(&hh);
            }
            int chunk = (bc + p) ^ (brow & 7);
            *reinterpret_cast<uint4*>(&Bs[buf][brow * BN + chunk * 8]) =
                make_uint4(h[0], h[1], h[2], h[3]);
        }
    };

    auto compute = [&](int buf) {
        const unsigned aBase = smem_addr(&As[buf][0]);
        const unsigned bBase = smem_addr(&Bs[buf][0]);
        const int lr    = (lane & 7) + ((lane >> 3) & 1) * 8;  // row within 16x16 A tile
        const int lcTop = ((lane >> 4) & 1) * 8;               // col half select
#pragma unroll
        for (int ks = 0; ks < 2; ks++) {
            unsigned a[2][4];
#pragma unroll
            for (int mi = 0; mi < 2; mi++) {
                int row = wm + mi * 16 + lr;
                int col = ks * 16 + lcTop;
                ldsm_x4(a[mi][0], a[mi][1], a[mi][2], a[mi][3],
                        aBase + (unsigned)(row * LDA + col) * 2u);
            }
            unsigned b[4][4];
            const int bk = ks * 16 + (lane & 7) + ((lane >> 3) & 1) * 8;
#pragma unroll
            for (int nt = 0; nt < 4; nt++) {
                int nn = wn + nt * 16 + lcTop;
                int chunk = (nn >> 3) ^ (bk & 7);
                ldsm_x4_t(b[nt][0], b[nt][1], b[nt][2], b[nt][3],
                          bBase + (unsigned)(bk * BN + chunk * 8) * 2u);
            }
#pragma unroll
            for (int mi = 0; mi < 2; mi++)
#pragma unroll
                for (int nj = 0; nj < 8; nj++)
                    mma16816(acc[mi][nj], a[mi], b[nj >> 1][(nj & 1) * 2],
                             b[nj >> 1][(nj & 1) * 2 + 1]);
        }
    };

    // prologue
    load_raw(0);
    store_smem(0);
    __syncthreads();

    int buf = 0;
    for (int it = 0; it < KT; ++it) {
        if (it + 1 < KT) load_raw(it + 1);   // gmem loads overlap with compute below
        compute(buf);
        if (it + 1 < KT) {
            __syncthreads();                 // everyone done reading buf^1 (two iters ago)
            store_smem(buf ^ 1);
            __syncthreads();
            buf ^= 1;
        }
    }

    // epilogue: fp32 fragment -> gmem
    const int erow  = m0 + wm + (lane >> 2);
    const int ecol0 = n0 + wn + (lane & 3) * 2;
#pragma unroll
    for (int mi = 0; mi < 2; mi++) {
#pragma unroll
        for (int nj = 0; nj < 8; nj++) {
            int r = erow + mi * 16;
            int c = ecol0 + nj * 8;
            *reinterpret_cast<float2*>(&out[(size_t)r * N_DIM + c]) =
                make_float2(acc[mi][nj][0], acc[mi][nj][1]);
            *reinterpret_cast<float2*>(&out[(size_t)(r + 8) * N_DIM + c]) =
                make_float2(acc[mi][nj][2], acc[mi][nj][3]);
        }
    }
}

extern "C" void kernel_launch(void* const* d_in, const int* in_sizes, int n_in,
                              void* d_out, int out_size) {
    (void)in_sizes; (void)n_in; (void)out_size;
    const float* x  = (const float*)d_in[0];
    const int*   qw = (const int*)d_in[1];
    const int*   qz = (const int*)d_in[2];
    const float* sc = (const float*)d_in[3];
    // d_in[4] = group_size (128), hardcoded

    dim3 grid(N_DIM / BN, M_DIM / BM);   // (86, 16)
    awq_gemm_kernel<<<grid, 256>>>(x, qw, qz, sc, (float*)d_out);
}

// round 7
// speedup vs baseline: 2.0174x; 2.0174x over previous
#include <cuda_runtime.h>
#include <cuda_fp16.h>
#include <cstdint>

#define M_DIM 2048
#define K_DIM 4096
#define N_DIM 11008
#define NPACK (N_DIM / 8)      // 1376

// GEMM tiling
#define BM 128
#define BN 256
#define BK 64
#define KCHUNKS (K_DIM / BK)   // 64
#define STAGES 3
#define A_STAGE_BYTES (BM * BK * 2)               // 16384
#define B_STAGE_BYTES (BN * BK * 2)               // 32768
#define STAGE_BYTES (A_STAGE_BYTES + B_STAGE_BYTES)
#define SMEM_BYTES (STAGES * STAGE_BYTES)         // 147456

// Scratch (device globals: allocation-free scratch)
__device__ __align__(1024) __half g_xh[(size_t)M_DIM * K_DIM];   // 16.8 MB, [m][k]
__device__ __align__(1024) __half g_wt[(size_t)N_DIM * K_DIM];   // 90 MB,  [n][k]

// ---------------- PTX helpers ----------------
__device__ __forceinline__ uint32_t smem_u32(const void* p) {
    uint32_t a;
    asm("{ .reg .u64 t; cvta.to.shared.u64 t, %1; cvt.u32.u64 %0, t; }" : "=r"(a) : "l"(p));
    return a;
}

__device__ __forceinline__ void cp_async16(uint32_t dst, const void* src) {
    asm volatile("cp.async.cg.shared.global [%0], [%1], 16;" :: "r"(dst), "l"(src) : "memory");
}
__device__ __forceinline__ void cp_commit() {
    asm volatile("cp.async.commit_group;" ::: "memory");
}
template <int N>
__device__ __forceinline__ void cp_wait() {
    asm volatile("cp.async.wait_group %0;" :: "n"(N) : "memory");
}

__device__ __forceinline__ void ldsm_x4(unsigned& r0, unsigned& r1, unsigned& r2, unsigned& r3,
                                        uint32_t addr) {
    asm volatile("ldmatrix.sync.aligned.m8n8.x4.shared.b16 {%0,%1,%2,%3}, [%4];"
                 : "=r"(r0), "=r"(r1), "=r"(r2), "=r"(r3) : "r"(addr));
}

__device__ __forceinline__ void mma16816(float* c, const unsigned* a, unsigned b0, unsigned b1) {
    asm volatile(
        "mma.sync.aligned.m16n8k16.row.col.f32.f16.f16.f32 "
        "{%0,%1,%2,%3}, {%4,%5,%6,%7}, {%8,%9}, {%0,%1,%2,%3};"
        : "+f"(c[0]), "+f"(c[1]), "+f"(c[2]), "+f"(c[3])
        : "r"(a[0]), "r"(a[1]), "r"(a[2]), "r"(a[3]), "r"(b0), "r"(b1));
}

// ---------------- Kernel 1: x fp32 -> fp16 ----------------
__global__ void convert_x_kernel(const float* __restrict__ x) {
    size_t id = (size_t)blockIdx.x * 256 + threadIdx.x;   // 1,048,576 ids, 8 halves each
    const float4* xp = reinterpret_cast<const float4*>(x) + id * 2;
    float4 a = xp[0], b = xp[1];
    __half2 h0 = __floats2half2_rn(a.x, a.y);
    __half2 h1 = __floats2half2_rn(a.z, a.w);
    __half2 h2 = __floats2half2_rn(b.x, b.y);
    __half2 h3 = __floats2half2_rn(b.z, b.w);
    uint4 o = make_uint4(*(uint32_t*)&h0, *(uint32_t*)&h1, *(uint32_t*)&h2, *(uint32_t*)&h3);
    reinterpret_cast<uint4*>(g_xh)[id] = o;
}

// ---------------- Kernel 2: AWQ dequant -> W_t[n][k] fp16 (once) ----------------
// thread: one packed column c (8 n's) x 16 consecutive k's
__global__ void dequant_kernel(const int* __restrict__ qw, const int* __restrict__ qz,
                               const float* __restrict__ sc) {
    int id = blockIdx.x * 256 + threadIdx.x;    // 0 .. 352255
    int c  = id % NPACK;
    int kb = id / NPACK;                         // 0..255
    int k0 = kb * 16;
    int g  = kb >> 3;                            // 128 k per group
    int n0 = c * 8;

    // zeros: magic-biased half2 pairs (value z + 1024)
    uint32_t zv = (uint32_t)qz[(size_t)g * NPACK + c];
    uint32_t zb[4];
#pragma unroll
    for (int p = 0; p < 4; p++)
        zb[p] = ((zv >> (4 * p)) & 0x000F000Fu) | 0x64006400u;

    const float* sp = sc + (size_t)g * N_DIM + n0;
    float4 s03 = *reinterpret_cast<const float4*>(sp);
    float4 s47 = *reinterpret_cast<const float4*>(sp + 4);
    __half2 sh[4] = { __floats2half2_rn(s03.x, s03.y), __floats2half2_rn(s03.z, s03.w),
                      __floats2half2_rn(s47.x, s47.y), __floats2half2_rn(s47.z, s47.w) };

    uint32_t w[16][4];
#pragma unroll
    for (int j = 0; j < 16; j++) {
        uint32_t v = (uint32_t)qw[(size_t)(k0 + j) * NPACK + c];
#pragma unroll
        for (int p = 0; p < 4; p++) {
            uint32_t qb = ((v >> (4 * p)) & 0x000F000Fu) | 0x64006400u;
            __half2 hq = *(__half2*)&qb;
            __half2 hz = *(__half2*)&zb[p];
            __half2 hw = __hmul2(__hsub2(hq, hz), sh[p]);   // sub exact; one mul rounding
            w[j][p] = *(uint32_t*)&hw;
        }
    }

    // transpose 16k x 8n -> 8 rows (n) of 16 k-contiguous halves
#pragma unroll
    for (int p = 0; p < 4; p++) {
        uint32_t lo[8], hi[8];
#pragma unroll
        for (int j = 0; j < 8; j++) {
            lo[j] = __byte_perm(w[2 * j][p], w[2 * j + 1][p], 0x5410);  // n = 2p
            hi[j] = __byte_perm(w[2 * j][p], w[2 * j + 1][p], 0x7632);  // n = 2p+1
        }
        __half* r0 = g_wt + (size_t)(n0 + 2 * p) * K_DIM + k0;
        __half* r1 = g_wt + (size_t)(n0 + 2 * p + 1) * K_DIM + k0;
        reinterpret_cast<uint4*>(r0)[0] = make_uint4(lo[0], lo[1], lo[2], lo[3]);
        reinterpret_cast<uint4*>(r0)[1] = make_uint4(lo[4], lo[5], lo[6], lo[7]);
        reinterpret_cast<uint4*>(r1)[0] = make_uint4(hi[0], hi[1], hi[2], hi[3]);
        reinterpret_cast<uint4*>(r1)[1] = make_uint4(hi[4], hi[5], hi[6], hi[7]);
    }
}

// ---------------- Kernel 3: HMMA GEMM with cp.async pipeline ----------------
// C[128x256] per CTA; 8 warps as 2(m) x 4(n), warp tile 64x64.
__global__ void __launch_bounds__(256, 1)
gemm_kernel(float* __restrict__ out) {
    extern __shared__ __align__(1024) char smem[];
    const uint32_t sbase = smem_u32(smem);
    const int tid = threadIdx.x;
    const int warp = tid >> 5, lane = tid & 31;
    const int m0 = blockIdx.y * BM;
    const int n0 = blockIdx.x * BN;
    const int wm = (warp & 1) * 64;
    const int wn = (warp >> 1) * 64;

    // cp.async mapping: 16B chunk per thread; row r, chunk col c (swizzled c^(r&7))
    const int lr = tid >> 3;          // 0..31
    const int lc = tid & 7;           // 0..7

    auto load_stage = [&](int slot, int kc) {
        const int k0 = kc * BK;
        const uint32_t sa = sbase + slot * STAGE_BYTES;
        const uint32_t sb = sa + A_STAGE_BYTES;
        const __half* gA = g_xh + (size_t)m0 * K_DIM + k0;
        const __half* gB = g_wt + (size_t)n0 * K_DIM + k0;
#pragma unroll
        for (int i = 0; i < 4; i++) {           // A: 128 rows
            int r = lr + i * 32;
            cp_async16(sa + r * 128 + ((lc ^ (r & 7)) * 16), gA + (size_t)r * K_DIM + lc * 8);
        }
#pragma unroll
        for (int i = 0; i < 8; i++) {           // B: 256 rows
            int r = lr + i * 32;
            cp_async16(sb + r * 128 + ((lc ^ (r & 7)) * 16), gB + (size_t)r * K_DIM + lc * 8);
        }
    };

    float acc[4][8][4];
#pragma unroll
    for (int i = 0; i < 4; i++)
#pragma unroll
        for (int j = 0; j < 8; j++)
#pragma unroll
            for (int q = 0; q < 4; q++) acc[i][j][q] = 0.f;

    // prologue: 2 stages in flight
    load_stage(0, 0); cp_commit();
    load_stage(1, 1); cp_commit();

    // ldmatrix lane address components
    const int aRow = (lane & 15);              // row within 16-row block
    const int aCol = (lane >> 4);              // 0/1 -> +8 halves (chunk +1)
    const int bRow = (lane & 7) + ((lane & 16) >> 1);  // (lane&7) + 8*(lane>=16)
    const int bCol = (lane >> 3) & 1;          // chunk +1 select

    for (int it = 0; it < KCHUNKS; ++it) {
        cp_wait<1>();
        __syncthreads();
        if (it + 2 < KCHUNKS) load_stage((it + 2) % STAGES, it + 2);
        cp_commit();

        const uint32_t sa = sbase + (it % STAGES) * STAGE_BYTES;
        const uint32_t sb = sa + A_STAGE_BYTES;
#pragma unroll
        for (int ks = 0; ks < 4; ks++) {       // 4 x k16
            unsigned a[4][4];
#pragma unroll
            for (int mi = 0; mi < 4; mi++) {
                int row = wm + mi * 16 + aRow;
                int ch  = (ks * 2 + aCol) ^ (row & 7);
                ldsm_x4(a[mi][0], a[mi][1], a[mi][2], a[mi][3],
                        sa + row * 128 + ch * 16);
            }
            unsigned b[4][4];
#pragma unroll
            for (int nb = 0; nb < 4; nb++) {
                int row = wn + nb * 16 + bRow;
                int ch  = (ks * 2 + bCol) ^ (row & 7);
                ldsm_x4(b[nb][0], b[nb][1], b[nb][2], b[nb][3],
                        sb + row * 128 + ch * 16);
            }
#pragma unroll
            for (int mi = 0; mi < 4; mi++)
#pragma unroll
                for (int nj = 0; nj < 8; nj++)
                    mma16816(acc[mi][nj], a[mi],
                             b[nj >> 1][(nj & 1) * 2], b[nj >> 1][(nj & 1) * 2 + 1]);
        }
    }

    // epilogue: fragments -> gmem (float2 per quad)
    const int erow  = m0 + wm + (lane >> 2);
    const int ecol0 = n0 + wn + (lane & 3) * 2;
#pragma unroll
    for (int mi = 0; mi < 4; mi++) {
#pragma unroll
        for (int nj = 0; nj < 8; nj++) {
            int r = erow + mi * 16;
            int c = ecol0 + nj * 8;
            *reinterpret_cast<float2*>(&out[(size_t)r * N_DIM + c]) =
                make_float2(acc[mi][nj][0], acc[mi][nj][1]);
            *reinterpret_cast<float2*>(&out[(size_t)(r + 8) * N_DIM + c]) =
                make_float2(acc[mi][nj][2], acc[mi][nj][3]);
        }
    }
}

// ---------------- host ----------------
extern "C" void kernel_launch(void* const* d_in, const int* in_sizes, int n_in,
                              void* d_out, int out_size) {
    (void)in_sizes; (void)n_in; (void)out_size;
    const float* x  = (const float*)d_in[0];
    const int*   qw = (const int*)d_in[1];
    const int*   qz = (const int*)d_in[2];
    const float* sc = (const float*)d_in[3];
    float* out = (float*)d_out;

    // Idempotent; no static guard (harness forbids call-count-dependent behavior).
    cudaFuncSetAttribute(gemm_kernel, cudaFuncAttributeMaxDynamicSharedMemorySize,
                         SMEM_BYTES);

    convert_x_kernel<<<(M_DIM * K_DIM / 8) / 256, 256>>>(x);
    dequant_kernel<<<(NPACK * (K_DIM / 16)) / 256, 256>>>(qw, qz, sc);
    gemm_kernel<<<dim3(N_DIM / BN, M_DIM / BM), 256, SMEM_BYTES>>>(out);
}

// round 8
// speedup vs baseline: 2.0404x; 1.0114x over previous
#include <cuda_runtime.h>
#include <cuda_fp16.h>
#include <cstdint>

#define M_DIM 2048
#define K_DIM 4096
#define N_DIM 11008
#define NPACK (N_DIM / 8)      // 1376

// GEMM tiling: 128x128 CTA tile, 2 CTAs/SM
#define BM 128
#define BN 128
#define BK 64
#define KCHUNKS (K_DIM / BK)   // 64
#define STAGES 3
#define A_STAGE_BYTES (BM * BK * 2)               // 16384
#define B_STAGE_BYTES (BN * BK * 2)               // 16384
#define STAGE_BYTES (A_STAGE_BYTES + B_STAGE_BYTES)
#define SMEM_BYTES (STAGES * STAGE_BYTES)         // 98304 -> 2 CTAs/SM

// Scratch (device globals: allocation-free scratch)
__device__ __align__(1024) __half g_xh[(size_t)M_DIM * K_DIM];   // 16.8 MB, [m][k]
__device__ __align__(1024) __half g_wt[(size_t)N_DIM * K_DIM];   // 90 MB,  [n][k]

// ---------------- PTX helpers ----------------
__device__ __forceinline__ uint32_t smem_u32(const void* p) {
    uint32_t a;
    asm("{ .reg .u64 t; cvta.to.shared.u64 t, %1; cvt.u32.u64 %0, t; }" : "=r"(a) : "l"(p));
    return a;
}

__device__ __forceinline__ void cp_async16(uint32_t dst, const void* src) {
    asm volatile("cp.async.cg.shared.global [%0], [%1], 16;" :: "r"(dst), "l"(src) : "memory");
}
__device__ __forceinline__ void cp_commit() {
    asm volatile("cp.async.commit_group;" ::: "memory");
}
template <int N>
__device__ __forceinline__ void cp_wait() {
    asm volatile("cp.async.wait_group %0;" :: "n"(N) : "memory");
}

__device__ __forceinline__ void ldsm_x4(unsigned& r0, unsigned& r1, unsigned& r2, unsigned& r3,
                                        uint32_t addr) {
    asm volatile("ldmatrix.sync.aligned.m8n8.x4.shared.b16 {%0,%1,%2,%3}, [%4];"
                 : "=r"(r0), "=r"(r1), "=r"(r2), "=r"(r3) : "r"(addr));
}

__device__ __forceinline__ void mma16816(float* c, const unsigned* a, unsigned b0, unsigned b1) {
    asm volatile(
        "mma.sync.aligned.m16n8k16.row.col.f32.f16.f16.f32 "
        "{%0,%1,%2,%3}, {%4,%5,%6,%7}, {%8,%9}, {%0,%1,%2,%3};"
        : "+f"(c[0]), "+f"(c[1]), "+f"(c[2]), "+f"(c[3])
        : "r"(a[0]), "r"(a[1]), "r"(a[2]), "r"(a[3]), "r"(b0), "r"(b1));
}

// ---------------- Kernel 1: x fp32 -> fp16 ----------------
__global__ void convert_x_kernel(const float* __restrict__ x) {
    size_t id = (size_t)blockIdx.x * 256 + threadIdx.x;   // 1,048,576 ids, 8 halves each
    const float4* xp = reinterpret_cast<const float4*>(x) + id * 2;
    float4 a = xp[0], b = xp[1];
    __half2 h0 = __floats2half2_rn(a.x, a.y);
    __half2 h1 = __floats2half2_rn(a.z, a.w);
    __half2 h2 = __floats2half2_rn(b.x, b.y);
    __half2 h3 = __floats2half2_rn(b.z, b.w);
    uint4 o = make_uint4(*(uint32_t*)&h0, *(uint32_t*)&h1, *(uint32_t*)&h2, *(uint32_t*)&h3);
    reinterpret_cast<uint4*>(g_xh)[id] = o;
}

// ---------------- Kernel 2: AWQ dequant -> W_t[n][k] fp16 (once) ----------------
// thread: one packed column c (8 n's) x 16 consecutive k's
__global__ void dequant_kernel(const int* __restrict__ qw, const int* __restrict__ qz,
                               const float* __restrict__ sc) {
    int id = blockIdx.x * 256 + threadIdx.x;    // 0 .. 352255
    int c  = id % NPACK;
    int kb = id / NPACK;                         // 0..255
    int k0 = kb * 16;
    int g  = kb >> 3;                            // 128 k per group
    int n0 = c * 8;

    // zeros: magic-biased half2 pairs (value z + 1024)
    uint32_t zv = (uint32_t)qz[(size_t)g * NPACK + c];
    uint32_t zb[4];
#pragma unroll
    for (int p = 0; p < 4; p++)
        zb[p] = ((zv >> (4 * p)) & 0x000F000Fu) | 0x64006400u;

    const float* sp = sc + (size_t)g * N_DIM + n0;
    float4 s03 = *reinterpret_cast<const float4*>(sp);
    float4 s47 = *reinterpret_cast<const float4*>(sp + 4);
    __half2 sh[4] = { __floats2half2_rn(s03.x, s03.y), __floats2half2_rn(s03.z, s03.w),
                      __floats2half2_rn(s47.x, s47.y), __floats2half2_rn(s47.z, s47.w) };

    uint32_t w[16][4];
#pragma unroll
    for (int j = 0; j < 16; j++) {
        uint32_t v = (uint32_t)qw[(size_t)(k0 + j) * NPACK + c];
#pragma unroll
        for (int p = 0; p < 4; p++) {
            uint32_t qb = ((v >> (4 * p)) & 0x000F000Fu) | 0x64006400u;
            __half2 hq = *(__half2*)&qb;
            __half2 hz = *(__half2*)&zb[p];
            __half2 hw = __hmul2(__hsub2(hq, hz), sh[p]);   // sub exact; one mul rounding
            w[j][p] = *(uint32_t*)&hw;
        }
    }

    // transpose 16k x 8n -> 8 rows (n) of 16 k-contiguous halves
#pragma unroll
    for (int p = 0; p < 4; p++) {
        uint32_t lo[8], hi[8];
#pragma unroll
        for (int j = 0; j < 8; j++) {
            lo[j] = __byte_perm(w[2 * j][p], w[2 * j + 1][p], 0x5410);  // n = 2p
            hi[j] = __byte_perm(w[2 * j][p], w[2 * j + 1][p], 0x7632);  // n = 2p+1
        }
        __half* r0 = g_wt + (size_t)(n0 + 2 * p) * K_DIM + k0;
        __half* r1 = g_wt + (size_t)(n0 + 2 * p + 1) * K_DIM + k0;
        reinterpret_cast<uint4*>(r0)[0] = make_uint4(lo[0], lo[1], lo[2], lo[3]);
        reinterpret_cast<uint4*>(r0)[1] = make_uint4(lo[4], lo[5], lo[6], lo[7]);
        reinterpret_cast<uint4*>(r1)[0] = make_uint4(hi[0], hi[1], hi[2], hi[3]);
        reinterpret_cast<uint4*>(r1)[1] = make_uint4(hi[4], hi[5], hi[6], hi[7]);
    }
}

// ---------------- Kernel 3: HMMA GEMM with cp.async pipeline ----------------
// C[128x128] per CTA; 8 warps as 2(m) x 4(n), warp tile 64x32; 2 CTAs/SM.
__global__ void __launch_bounds__(256, 2)
gemm_kernel(float* __restrict__ out) {
    extern __shared__ __align__(1024) char smem[];
    const uint32_t sbase = smem_u32(smem);
    const int tid = threadIdx.x;
    const int warp = tid >> 5, lane = tid & 31;
    const int m0 = blockIdx.y * BM;
    const int n0 = blockIdx.x * BN;
    const int wm = (warp & 1) * 64;
    const int wn = (warp >> 1) * 32;

    // cp.async mapping: 16B chunk per thread; row r, chunk col c (swizzled c^(r&7))
    const int lr = tid >> 3;          // 0..31
    const int lc = tid & 7;           // 0..7

    auto load_stage = [&](int slot, int kc) {
        const int k0 = kc * BK;
        const uint32_t sa = sbase + slot * STAGE_BYTES;
        const uint32_t sb = sa + A_STAGE_BYTES;
        const __half* gA = g_xh + (size_t)m0 * K_DIM + k0;
        const __half* gB = g_wt + (size_t)n0 * K_DIM + k0;
#pragma unroll
        for (int i = 0; i < 4; i++) {           // A: 128 rows
            int r = lr + i * 32;
            cp_async16(sa + r * 128 + ((lc ^ (r & 7)) * 16), gA + (size_t)r * K_DIM + lc * 8);
        }
#pragma unroll
        for (int i = 0; i < 4; i++) {           // B: 128 rows
            int r = lr + i * 32;
            cp_async16(sb + r * 128 + ((lc ^ (r & 7)) * 16), gB + (size_t)r * K_DIM + lc * 8);
        }
    };

    float acc[4][4][4];
#pragma unroll
    for (int i = 0; i < 4; i++)
#pragma unroll
        for (int j = 0; j < 4; j++)
#pragma unroll
            for (int q = 0; q < 4; q++) acc[i][j][q] = 0.f;

    // prologue: 2 stages in flight
    load_stage(0, 0); cp_commit();
    load_stage(1, 1); cp_commit();

    // ldmatrix lane address components
    const int aRow = (lane & 15);              // row within 16-row block
    const int aCol = (lane >> 4);              // 0/1 -> +8 halves (chunk +1)
    const int bRow = (lane & 7) + ((lane & 16) >> 1);  // (lane&7) + 8*(lane>=16)
    const int bCol = (lane >> 3) & 1;          // chunk +1 select

    for (int it = 0; it < KCHUNKS; ++it) {
        cp_wait<1>();
        __syncthreads();
        if (it + 2 < KCHUNKS) load_stage((it + 2) % STAGES, it + 2);
        cp_commit();

        const uint32_t sa = sbase + (it % STAGES) * STAGE_BYTES;
        const uint32_t sb = sa + A_STAGE_BYTES;
#pragma unroll
        for (int ks = 0; ks < 4; ks++) {       // 4 x k16
            unsigned a[4][4];
#pragma unroll
            for (int mi = 0; mi < 4; mi++) {
                int row = wm + mi * 16 + aRow;
                int ch  = (ks * 2 + aCol) ^ (row & 7);
                ldsm_x4(a[mi][0], a[mi][1], a[mi][2], a[mi][3],
                        sa + row * 128 + ch * 16);
            }
            unsigned b[2][4];
#pragma unroll
            for (int nb = 0; nb < 2; nb++) {
                int row = wn + nb * 16 + bRow;
                int ch  = (ks * 2 + bCol) ^ (row & 7);
                ldsm_x4(b[nb][0], b[nb][1], b[nb][2], b[nb][3],
                        sb + row * 128 + ch * 16);
            }
#pragma unroll
            for (int mi = 0; mi < 4; mi++)
#pragma unroll
                for (int nj = 0; nj < 4; nj++)
                    mma16816(acc[mi][nj], a[mi],
                             b[nj >> 1][(nj & 1) * 2], b[nj >> 1][(nj & 1) * 2 + 1]);
        }
    }

    // epilogue: fragments -> gmem (float2 per quad)
    const int erow  = m0 + wm + (lane >> 2);
    const int ecol0 = n0 + wn + (lane & 3) * 2;
#pragma unroll
    for (int mi = 0; mi < 4; mi++) {
#pragma unroll
        for (int nj = 0; nj < 4; nj++) {
            int r = erow + mi * 16;
            int c = ecol0 + nj * 8;
            *reinterpret_cast<float2*>(&out[(size_t)r * N_DIM + c]) =
                make_float2(acc[mi][nj][0], acc[mi][nj][1]);
            *reinterpret_cast<float2*>(&out[(size_t)(r + 8) * N_DIM + c]) =
                make_float2(acc[mi][nj][2], acc[mi][nj][3]);
        }
    }
}

// ---------------- host ----------------
extern "C" void kernel_launch(void* const* d_in, const int* in_sizes, int n_in,
                              void* d_out, int out_size) {
    (void)in_sizes; (void)n_in; (void)out_size;
    const float* x  = (const float*)d_in[0];
    const int*   qw = (const int*)d_in[1];
    const int*   qz = (const int*)d_in[2];
    const float* sc = (const float*)d_in[3];
    float* out = (float*)d_out;

    // Idempotent; no static guard (harness forbids call-count-dependent behavior).
    cudaFuncSetAttribute(gemm_kernel, cudaFuncAttributeMaxDynamicSharedMemorySize,
                         SMEM_BYTES);

    convert_x_kernel<<<(M_DIM * K_DIM / 8) / 256, 256>>>(x);
    dequant_kernel<<<(NPACK * (K_DIM / 16)) / 256, 256>>>(qw, qz, sc);
    gemm_kernel<<<dim3(N_DIM / BN, M_DIM / BM), 256, SMEM_BYTES>>>(out);
}

// round 9
// speedup vs baseline: 2.2205x; 1.0883x over previous
#include <cuda_runtime.h>
#include <cuda_fp16.h>
#include <cstdint>

#define M_DIM 2048
#define K_DIM 4096
#define N_DIM 11008
#define NPACK (N_DIM / 8)      // 1376

// GEMM tiling: 128x128 CTA tile, 2 CTAs/SM
#define BM 128
#define BN 128
#define BK 64
#define KCHUNKS (K_DIM / BK)   // 64
#define STAGES 3
#define A_STAGE_BYTES (BM * BK * 2)               // 16384
#define B_STAGE_BYTES (BK * BN * 2)               // 16384
#define STAGE_BYTES (A_STAGE_BYTES + B_STAGE_BYTES)
#define SMEM_BYTES (STAGES * STAGE_BYTES)         // 98304 -> 2 CTAs/SM

// Scratch (device globals: allocation-free scratch)
__device__ __align__(1024) __half g_xh[(size_t)M_DIM * K_DIM];   // 16.8 MB, [m][k]
__device__ __align__(1024) __half g_w [(size_t)K_DIM * N_DIM];   // 90 MB,  [k][n]

// ---------------- PTX helpers ----------------
__device__ __forceinline__ uint32_t smem_u32(const void* p) {
    uint32_t a;
    asm("{ .reg .u64 t; cvta.to.shared.u64 t, %1; cvt.u32.u64 %0, t; }" : "=r"(a) : "l"(p));
    return a;
}

__device__ __forceinline__ void cp_async16(uint32_t dst, const void* src) {
    asm volatile("cp.async.cg.shared.global [%0], [%1], 16;" :: "r"(dst), "l"(src) : "memory");
}
__device__ __forceinline__ void cp_commit() {
    asm volatile("cp.async.commit_group;" ::: "memory");
}
template <int N>
__device__ __forceinline__ void cp_wait() {
    asm volatile("cp.async.wait_group %0;" :: "n"(N) : "memory");
}

__device__ __forceinline__ void ldsm_x4(unsigned& r0, unsigned& r1, unsigned& r2, unsigned& r3,
                                        uint32_t addr) {
    asm volatile("ldmatrix.sync.aligned.m8n8.x4.shared.b16 {%0,%1,%2,%3}, [%4];"
                 : "=r"(r0), "=r"(r1), "=r"(r2), "=r"(r3) : "r"(addr));
}
__device__ __forceinline__ void ldsm_x4_t(unsigned& r0, unsigned& r1, unsigned& r2, unsigned& r3,
                                          uint32_t addr) {
    asm volatile("ldmatrix.sync.aligned.m8n8.x4.trans.shared.b16 {%0,%1,%2,%3}, [%4];"
                 : "=r"(r0), "=r"(r1), "=r"(r2), "=r"(r3) : "r"(addr));
}

__device__ __forceinline__ void mma16816(float* c, const unsigned* a, unsigned b0, unsigned b1) {
    asm volatile(
        "mma.sync.aligned.m16n8k16.row.col.f32.f16.f16.f32 "
        "{%0,%1,%2,%3}, {%4,%5,%6,%7}, {%8,%9}, {%0,%1,%2,%3};"
        : "+f"(c[0]), "+f"(c[1]), "+f"(c[2]), "+f"(c[3])
        : "r"(a[0]), "r"(a[1]), "r"(a[2]), "r"(a[3]), "r"(b0), "r"(b1));
}

// ---------------- Kernel 1: x fp32 -> fp16 ----------------
__global__ void convert_x_kernel(const float* __restrict__ x) {
    size_t id = (size_t)blockIdx.x * 256 + threadIdx.x;   // 1,048,576 ids, 8 halves each
    const float4* xp = reinterpret_cast<const float4*>(x) + id * 2;
    float4 a = xp[0], b = xp[1];
    __half2 h0 = __floats2half2_rn(a.x, a.y);
    __half2 h1 = __floats2half2_rn(a.z, a.w);
    __half2 h2 = __floats2half2_rn(b.x, b.y);
    __half2 h3 = __floats2half2_rn(b.z, b.w);
    uint4 o = make_uint4(*(uint32_t*)&h0, *(uint32_t*)&h1, *(uint32_t*)&h2, *(uint32_t*)&h3);
    reinterpret_cast<uint4*>(g_xh)[id] = o;
}

// ---------------- Kernel 2: AWQ dequant -> W[k][n] fp16 (no transpose) ----------------
// thread: one packed column c (8 n's) x 16 consecutive k's.
// Pair p of a word = logical elements (2p, 2p+1) -> word expands to 8 n-contiguous
// halves in order -> single uint4 store per word into row k.
__global__ void dequant_kernel(const int* __restrict__ qw, const int* __restrict__ qz,
                               const float* __restrict__ sc) {
    int id = blockIdx.x * 256 + threadIdx.x;    // 0 .. 352255
    int c  = id % NPACK;
    int kb = id / NPACK;                         // 0..255
    int k0 = kb * 16;
    int g  = kb >> 3;                            // 128 k per group
    int n0 = c * 8;

    // zeros: magic-biased half2 pairs (value z + 1024)
    uint32_t zv = (uint32_t)qz[(size_t)g * NPACK + c];
    uint32_t zb[4];
#pragma unroll
    for (int p = 0; p < 4; p++)
        zb[p] = ((zv >> (4 * p)) & 0x000F000Fu) | 0x64006400u;

    const float* sp = sc + (size_t)g * N_DIM + n0;
    float4 s03 = *reinterpret_cast<const float4*>(sp);
    float4 s47 = *reinterpret_cast<const float4*>(sp + 4);
    __half2 sh[4] = { __floats2half2_rn(s03.x, s03.y), __floats2half2_rn(s03.z, s03.w),
                      __floats2half2_rn(s47.x, s47.y), __floats2half2_rn(s47.z, s47.w) };

#pragma unroll
    for (int j = 0; j < 16; j++) {
        uint32_t v = (uint32_t)qw[(size_t)(k0 + j) * NPACK + c];
        uint32_t o[4];
#pragma unroll
        for (int p = 0; p < 4; p++) {
            uint32_t qb = ((v >> (4 * p)) & 0x000F000Fu) | 0x64006400u;
            __half2 hq = *(__half2*)&qb;
            __half2 hz = *(__half2*)&zb[p];
            __half2 hw = __hmul2(__hsub2(hq, hz), sh[p]);   // sub exact; one mul rounding
            o[p] = *(uint32_t*)&hw;
        }
        *reinterpret_cast<uint4*>(g_w + (size_t)(k0 + j) * N_DIM + n0) =
            make_uint4(o[0], o[1], o[2], o[3]);
    }
}

// ---------------- Kernel 3: HMMA GEMM with cp.async pipeline ----------------
// C[128x128] per CTA; 8 warps as 2(m) x 4(n), warp tile 64x32; 2 CTAs/SM.
// A tile [m][k] (non-trans ldmatrix); B tile [k][n] (trans ldmatrix, R1-verified).
__global__ void __launch_bounds__(256, 2)
gemm_kernel(float* __restrict__ out) {
    extern __shared__ __align__(1024) char smem[];
    const uint32_t sbase = smem_u32(smem);
    const int tid = threadIdx.x;
    const int warp = tid >> 5, lane = tid & 31;
    const int m0 = blockIdx.y * BM;
    const int n0 = blockIdx.x * BN;
    const int wm = (warp & 1) * 64;
    const int wn = (warp >> 1) * 32;

    // staging maps: 16B chunk per thread
    const int lr = tid >> 3;          // 0..31
    const int lc = tid & 7;           // 0..7

    auto load_stage = [&](int slot, int kc) {
        const int k0 = kc * BK;
        const uint32_t sa = sbase + slot * STAGE_BYTES;
        const uint32_t sb = sa + A_STAGE_BYTES;
        const __half* gA = g_xh + (size_t)m0 * K_DIM + k0;
        const __half* gB = g_w + (size_t)k0 * N_DIM + n0;
        // A: 128 rows x 8 chunks (row = 128B), swizzle chunk ^ (row&7)
#pragma unroll
        for (int i = 0; i < 4; i++) {
            int r = lr + i * 32;
            cp_async16(sa + r * 128 + ((lc ^ (r & 7)) * 16), gA + (size_t)r * K_DIM + lc * 8);
        }
        // B: 64 rows x 16 chunks (row = 256B), swizzle chunk ^ (row&7) (low 3 bits)
#pragma unroll
        for (int ri = 0; ri < 2; ri++) {
#pragma unroll
            for (int ci = 0; ci < 2; ci++) {
                int r  = lr + ri * 32;
                int ch = lc + ci * 8;
                cp_async16(sb + r * 256 + ((ch ^ (r & 7)) * 16),
                           gB + (size_t)r * N_DIM + ch * 8);
            }
        }
    };

    float acc[4][4][4];
#pragma unroll
    for (int i = 0; i < 4; i++)
#pragma unroll
        for (int j = 0; j < 4; j++)
#pragma unroll
            for (int q = 0; q < 4; q++) acc[i][j][q] = 0.f;

    // prologue: 2 stages in flight
    load_stage(0, 0); cp_commit();
    load_stage(1, 1); cp_commit();

    // ldmatrix lane address components
    const int aRow  = (lane & 15);             // row within 16-row block
    const int aCol  = (lane >> 4);             // 0/1 -> +8 halves (chunk +1)
    const int bkLow = (lane & 7) + ((lane >> 3) & 1) * 8;  // k row within 16
    const int lcTop = ((lane >> 4) & 1) * 8;   // n half select

    for (int it = 0; it < KCHUNKS; ++it) {
        cp_wait<1>();
        __syncthreads();
        if (it + 2 < KCHUNKS) load_stage((it + 2) % STAGES, it + 2);
        cp_commit();

        const uint32_t sa = sbase + (it % STAGES) * STAGE_BYTES;
        const uint32_t sb = sa + A_STAGE_BYTES;
#pragma unroll
        for (int ks = 0; ks < 4; ks++) {       // 4 x k16
            unsigned a[4][4];
#pragma unroll
            for (int mi = 0; mi < 4; mi++) {
                int row = wm + mi * 16 + aRow;
                int ch  = (ks * 2 + aCol) ^ (row & 7);
                ldsm_x4(a[mi][0], a[mi][1], a[mi][2], a[mi][3],
                        sa + row * 128 + ch * 16);
            }
            unsigned b[2][4];
            const int bk = ks * 16 + bkLow;
#pragma unroll
            for (int nb = 0; nb < 2; nb++) {
                int nn = wn + nb * 16 + lcTop;
                int ch = (nn >> 3) ^ (bk & 7);
                ldsm_x4_t(b[nb][0], b[nb][1], b[nb][2], b[nb][3],
                          sb + bk * 256 + ch * 16);
            }
#pragma unroll
            for (int mi = 0; mi < 4; mi++)
#pragma unroll
                for (int nj = 0; nj < 4; nj++)
                    mma16816(acc[mi][nj], a[mi],
                             b[nj >> 1][(nj & 1) * 2], b[nj >> 1][(nj & 1) * 2 + 1]);
        }
    }

    // epilogue: fragments -> gmem (float2 per quad)
    const int erow  = m0 + wm + (lane >> 2);
    const int ecol0 = n0 + wn + (lane & 3) * 2;
#pragma unroll
    for (int mi = 0; mi < 4; mi++) {
#pragma unroll
        for (int nj = 0; nj < 4; nj++) {
            int r = erow + mi * 16;
            int c = ecol0 + nj * 8;
            *reinterpret_cast<float2*>(&out[(size_t)r * N_DIM + c]) =
                make_float2(acc[mi][nj][0], acc[mi][nj][1]);
            *reinterpret_cast<float2*>(&out[(size_t)(r + 8) * N_DIM + c]) =
                make_float2(acc[mi][nj][2], acc[mi][nj][3]);
        }
    }
}

// ---------------- host ----------------
extern "C" void kernel_launch(void* const* d_in, const int* in_sizes, int n_in,
                              void* d_out, int out_size) {
    (void)in_sizes; (void)n_in; (void)out_size;
    const float* x  = (const float*)d_in[0];
    const int*   qw = (const int*)d_in[1];
    const int*   qz = (const int*)d_in[2];
    const float* sc = (const float*)d_in[3];
    float* out = (float*)d_out;

    // Idempotent; no static guard (harness forbids call-count-dependent behavior).
    cudaFuncSetAttribute(gemm_kernel, cudaFuncAttributeMaxDynamicSharedMemorySize,
                         SMEM_BYTES);

    convert_x_kernel<<<(M_DIM * K_DIM / 8) / 256, 256>>>(x);
    dequant_kernel<<<(NPACK * (K_DIM / 16)) / 256, 256>>>(qw, qz, sc);
    gemm_kernel<<<dim3(N_DIM / BN, M_DIM / BM), 256, SMEM_BYTES>>>(out);
}